// round 10
// baseline (speedup 1.0000x reference)
#include <cuda_runtime.h>
#include <cuda_fp16.h>
#include <cstdint>

// CosSimilarity via fp16 mma.sync (legacy HMMA; tcgen05 unavailable: harness
// ptxas targets plain sm_103).
//  K1: normalize rows (x side pre-scaled by 1/TEMP=20) -> fp16 scratch.
//  K2: persistent HMMA GEMM. BM=BN=128, BK=64, 3 stages, mbarrier pipeline,
//      128-thread CTAs (4 warps, 2x2 of 64x64 warp tiles), 2 CTA/SM (= R8).
//      NEW (R10): mbarrier waits get an LDS fast-path. try_wait costs ~90cyc
//      even when already complete; a plain ld.shared peek of the phase bit is
//      ~29cyc. Phase-bit mask/polarity is runtime-calibrated with a probe
//      barrier (mask==0 -> falls back to try_wait; never corrupts).

#define NROWS 4096
#define DDIM  1024
#define BM 128
#define BN 128
#define BK 64
#define NSTAGE 3
#define KITERS (DDIM / BK)              // 16
#define STAGE_BYTES ((BM + BN) * 128)   // 32 KB
#define SMEM_ST0 1024
#define SMEM_DYN (SMEM_ST0 + NSTAGE * STAGE_BYTES)
#define NTILES ((NROWS / BM) * (NROWS / BN))   // 1024
#define GRID_P 296                      // 2 x 148 SMs
#define NTHREADS 128

__device__ __align__(1024) __half g_xh[NROWS * DDIM];
__device__ __align__(1024) __half g_yh[NROWS * DDIM];

__device__ __forceinline__ uint32_t smem_u32(const void* p) {
    uint32_t a;
    asm("{ .reg .u64 t; cvta.to.shared.u64 t, %1; cvt.u32.u64 %0, t; }" : "=r"(a) : "l"(p));
    return a;
}

#define CP_ASYNC16(dst, src) \
    asm volatile("cp.async.cg.shared.global [%0], [%1], 16;" :: "r"(dst), "l"(src))
#define CP_ASYNC_ARRIVE_NOINC(mbar) \
    asm volatile("cp.async.mbarrier.arrive.noinc.shared.b64 [%0];" :: "r"(mbar) : "memory")

#define MBAR_INIT(addr, cnt) \
    asm volatile("mbarrier.init.shared.b64 [%0], %1;" :: "r"(addr), "r"(cnt) : "memory")
#define MBAR_ARRIVE(addr) \
    asm volatile("mbarrier.arrive.shared.b64 _, [%0];" :: "r"(addr) : "memory")

// Full (sleep-capable) waits — the slow path.
#define MBAR_WAIT(addr, par) do {                                                  \
    uint32_t _m = (addr); uint32_t _p = (par); uint32_t _done;                     \
    asm volatile("{\n\t.reg .pred p;\n\t"                                          \
        "mbarrier.try_wait.parity.acquire.cta.shared::cta.b64 p, [%1], %2;\n\t"    \
        "selp.b32 %0, 1, 0, p;\n\t}"                                               \
        : "=r"(_done) : "r"(_m), "r"(_p) : "memory");                              \
    if (!_done) {                                                                  \
        asm volatile("{\n\t.reg .pred P1;\n\t"                                     \
            "WL_%=:\n\t"                                                           \
            "mbarrier.try_wait.parity.acquire.cta.shared::cta.b64 P1, [%0], %1, 0x989680;\n\t" \
            "@P1 bra.uni WD_%=;\n\t"                                               \
            "bra.uni WL_%=;\n\t"                                                   \
            "WD_%=:\n\t}" :: "r"(_m), "r"(_p) : "memory");                         \
    }                                                                              \
} while (0)

// LDS fast-path peek + fallback. done(par) <=> (cur & mask) != exp(par).
// mask/val0 calibrated at runtime; mask==0 degenerates to always-slow-path.
#define MBAR_WAIT_FASTCK(addr, par, mask, val0) do {                               \
    uint64_t _cur;                                                                 \
    asm volatile("ld.shared.u64 %0, [%1];" : "=l"(_cur) : "r"(addr) : "memory");   \
    uint64_t _exp = (par) ? ((val0) ^ (mask)) : (val0);                            \
    if ((_cur & (mask)) == _exp) { MBAR_WAIT(addr, par); }                         \
} while (0)

__device__ __forceinline__ uint32_t swz(uint32_t off) {
    return off ^ ((off >> 3) & 0x70);
}

__device__ __forceinline__ void ldsm_x4(uint32_t* r, uint32_t addr) {
    asm volatile("ldmatrix.sync.aligned.m8n8.x4.shared.b16 {%0,%1,%2,%3}, [%4];"
                 : "=r"(r[0]), "=r"(r[1]), "=r"(r[2]), "=r"(r[3]) : "r"(addr));
}

__device__ __forceinline__ void mma16816(float* c, const uint32_t* a, const uint32_t* b) {
    asm volatile(
        "mma.sync.aligned.m16n8k16.row.col.f32.f16.f16.f32 "
        "{%0,%1,%2,%3}, {%4,%5,%6,%7}, {%8,%9}, {%0,%1,%2,%3};"
        : "+f"(c[0]), "+f"(c[1]), "+f"(c[2]), "+f"(c[3])
        : "r"(a[0]), "r"(a[1]), "r"(a[2]), "r"(a[3]), "r"(b[0]), "r"(b[1]));
}

// ---------------------------------------------------------------------------
// Kernel 1: row normalization -> fp16 (one 256-thread block per row)
// ---------------------------------------------------------------------------
__global__ void norm_kernel(const float* __restrict__ x, const float* __restrict__ y) {
    int row = blockIdx.x;
    const float4* src; __half2* dst; float extra;
    if (row < NROWS) {
        src = (const float4*)(x + (size_t)row * DDIM);
        dst = (__half2*)(g_xh + (size_t)row * DDIM);
        extra = 20.0f;                  // 1/TEMP folded into x side
    } else {
        int r = row - NROWS;
        src = (const float4*)(y + (size_t)r * DDIM);
        dst = (__half2*)(g_yh + (size_t)r * DDIM);
        extra = 1.0f;
    }
    int t = threadIdx.x;
    float4 v = src[t];
    float ss = v.x * v.x + v.y * v.y + v.z * v.z + v.w * v.w;
    #pragma unroll
    for (int o = 16; o > 0; o >>= 1) ss += __shfl_xor_sync(0xffffffffu, ss, o);

    __shared__ float wss[8];
    __shared__ float sinv;
    if ((t & 31) == 0) wss[t >> 5] = ss;
    __syncthreads();
    if (t == 0) {
        float tot = 0.0f;
        #pragma unroll
        for (int i = 0; i < 8; i++) tot += wss[i];
        sinv = extra / fmaxf(sqrtf(tot), 1e-8f);
    }
    __syncthreads();
    float inv = sinv;
    dst[2 * t]     = __floats2half2_rn(v.x * inv, v.y * inv);
    dst[2 * t + 1] = __floats2half2_rn(v.z * inv, v.w * inv);
}

// ---------------------------------------------------------------------------
// Kernel 2: persistent HMMA GEMM, 4 warps/CTA, warp tile 64x64, 2 CTA/SM
// ---------------------------------------------------------------------------
__global__ void __launch_bounds__(NTHREADS, 2) gemm_kernel(float* __restrict__ C) {
    extern __shared__ __align__(1024) char smem[];
    const uint32_t smem_base = smem_u32(smem);
    const int tid = threadIdx.x;
    const int wid = tid >> 5;
    const int lid = tid & 31;

    const int wm = wid & 1;              // m band (64 rows each)
    const int wn = wid >> 1;             // n band (64 cols each)

    // smem header: full[s] @ +s*8 (s<3); empty[s] @ +24+s*8; probe @ +48;
    // calib mask @ +56, val0 @ +64.
    if (tid == 0) {
        #pragma unroll
        for (int s = 0; s < NSTAGE; s++) {
            MBAR_INIT(smem_base + s * 8, NTHREADS); // full: one noinc arrive/thread
            MBAR_INIT(smem_base + 24 + s * 8, 4);   // empty: one arrive/warp
        }
        // Probe: calibrate phase-bit mask & phase-0 value.
        MBAR_INIT(smem_base + 48, 1);
        uint64_t w0, w1;
        asm volatile("ld.shared.u64 %0, [%1];" : "=l"(w0) : "r"(smem_base + 48) : "memory");
        MBAR_ARRIVE(smem_base + 48);     // completes phase 0 (count=1)
        asm volatile("ld.shared.u64 %0, [%1];" : "=l"(w1) : "r"(smem_base + 48) : "memory");
        uint64_t mask = w0 ^ w1;
        asm volatile("st.shared.u64 [%0], %1;" :: "r"(smem_base + 56), "l"(mask) : "memory");
        asm volatile("st.shared.u64 [%0], %1;" :: "r"(smem_base + 64), "l"(w0 & mask) : "memory");
    }
    __syncthreads();
    uint64_t ph_mask, ph_v0;
    asm volatile("ld.shared.u64 %0, [%1];" : "=l"(ph_mask) : "r"(smem_base + 56));
    asm volatile("ld.shared.u64 %0, [%1];" : "=l"(ph_v0)   : "r"(smem_base + 64));

    // ldmatrix lane geometry
    const int g   = lid >> 3;
    const int rin = lid & 7;
    const int a_m  = (g & 1) * 8 + rin;
    const int a_kb = (g >> 1) * 16;
    const int b_n  = (g >> 1) * 8 + rin;
    const int b_kb = (g & 1) * 16;

    uint32_t a_rowoff[4], b_rowoff[4];
    #pragma unroll
    for (int t = 0; t < 4; t++)
        a_rowoff[t] = (uint32_t)(wm * 64 + t * 16 + a_m) * 128;
    #pragma unroll
    for (int p = 0; p < 4; p++)
        b_rowoff[p] = (uint32_t)(BM + wn * 64 + p * 16 + b_n) * 128;

    // Stage loader for (tile lt, k-slice lk): 2048 chunks / 128 thr = 16 each.
    auto load_stage = [&](int sbuf, int lt, int lk) {
        uint32_t sbase = smem_base + SMEM_ST0 + sbuf * STAGE_BYTES;
        const char* ag = (const char*)g_xh
            + ((size_t)(lt >> 5) * BM) * (DDIM * 2) + lk * (BK * 2);
        const char* bg = (const char*)g_yh
            + ((size_t)(lt & 31) * BN) * (DDIM * 2) + lk * (BK * 2);
        #pragma unroll
        for (int k = 0; k < 16; k++) {
            int i = tid + k * NTHREADS;
            int r = (i >> 3) & 127;
            int c = (i & 7) * 16;
            uint32_t off = swz((uint32_t)((i < 1024 ? r : BM + r) * 128 + c));
            const char* src = (i < 1024 ? ag : bg) + (size_t)r * (DDIM * 2) + c;
            CP_ASYNC16(sbase + off, src);
        }
        CP_ASYNC_ARRIVE_NOINC(smem_base + sbuf * 8);
    };

    float acc[4][8][4];
    #pragma unroll
    for (int mt = 0; mt < 4; mt++)
        #pragma unroll
        for (int nt = 0; nt < 8; nt++)
            #pragma unroll
            for (int q = 0; q < 4; q++)
                acc[mt][nt][q] = 0.0f;

    int tile = blockIdx.x;
    int lt = tile, lk = 0;
    // Prologue: stages 0,1 of first tile (fresh empty barriers: no wait needed)
    load_stage(0, lt, 0);
    load_stage(1, lt, 1);
    lk = 2;

    int sb = 0, fpar = 0;     // consumer: buffer + full-parity
    int lb = 2, epar = 1;     // producer: buffer + empty-parity (first waits pass)
    while (tile < NTILES) {
        for (int it = 0; it < KITERS; ++it) {
            // Producer: refill next buffer (waits only on 3-ago consumption)
            if (lt < NTILES) {
                MBAR_WAIT_FASTCK(smem_base + 24 + lb * 8, epar, ph_mask, ph_v0);
                load_stage(lb, lt, lk);
                if (++lk == KITERS) { lk = 0; lt += GRID_P; }
                if (++lb == NSTAGE) { lb = 0; epar ^= 1; }
            }

            // Consumer: wait for this stage's data
            MBAR_WAIT_FASTCK(smem_base + sb * 8, fpar, ph_mask, ph_v0);

            const uint32_t sbase = smem_base + SMEM_ST0 + sb * STAGE_BYTES;
            #pragma unroll
            for (int ks = 0; ks < 4; ks++) {
                const uint32_t kb = ks * 32;
                uint32_t a[4][4];
                #pragma unroll
                for (int t = 0; t < 4; t++)
                    ldsm_x4(a[t], sbase + swz(a_rowoff[t] + kb + a_kb));
                uint32_t b[8][2];
                #pragma unroll
                for (int p = 0; p < 4; p++) {
                    uint32_t r[4];
                    ldsm_x4(r, sbase + swz(b_rowoff[p] + kb + b_kb));
                    b[2 * p][0] = r[0]; b[2 * p][1] = r[1];
                    b[2 * p + 1][0] = r[2]; b[2 * p + 1][1] = r[3];
                }
                #pragma unroll
                for (int mt = 0; mt < 4; mt++)
                    #pragma unroll
                    for (int nt = 0; nt < 8; nt++)
                        mma16816(acc[mt][nt], a[mt], b[nt]);
            }
            // This warp is done reading stage sb
            __syncwarp();
            if (lid == 0) MBAR_ARRIVE(smem_base + 24 + sb * 8);
            if (++sb == NSTAGE) { sb = 0; fpar ^= 1; }
        }

        // Epilogue for this tile (overlaps in-flight loads of next tile)
        {
            const int rowA0 = (tile >> 5) * BM;
            const int rowB0 = (tile & 31) * BN;
            const int crow = rowA0 + wm * 64 + (lid >> 2);
            const int ccol = rowB0 + wn * 64 + (lid & 3) * 2;
            #pragma unroll
            for (int mt = 0; mt < 4; mt++) {
                #pragma unroll
                for (int nt = 0; nt < 8; nt++) {
                    float* p0 = C + (size_t)(crow + mt * 16) * NROWS + ccol + nt * 8;
                    float* p1 = p0 + 8 * NROWS;
                    *(float2*)p0 = make_float2(acc[mt][nt][0], acc[mt][nt][1]);
                    *(float2*)p1 = make_float2(acc[mt][nt][2], acc[mt][nt][3]);
                    acc[mt][nt][0] = 0.0f; acc[mt][nt][1] = 0.0f;
                    acc[mt][nt][2] = 0.0f; acc[mt][nt][3] = 0.0f;
                }
            }
        }
        tile += GRID_P;
    }
}

// ---------------------------------------------------------------------------
extern "C" void kernel_launch(void* const* d_in, const int* in_sizes, int n_in,
                              void* d_out, int out_size) {
    const float* x = (const float*)d_in[0];
    const float* y = (const float*)d_in[1];
    float* out = (float*)d_out;

    cudaFuncSetAttribute(gemm_kernel, cudaFuncAttributeMaxDynamicSharedMemorySize, SMEM_DYN);

    norm_kernel<<<2 * NROWS, 256>>>(x, y);
    gemm_kernel<<<GRID_P, NTHREADS, SMEM_DYN>>>(out);
}

// round 11
// speedup vs baseline: 1.0049x; 1.0049x over previous
#include <cuda_runtime.h>
#include <cuda_fp16.h>
#include <cstdint>

// CosSimilarity via fp16 mma.sync (legacy HMMA; tcgen05 unavailable: harness
// ptxas targets plain sm_103).
//  K1: normalize rows (x side pre-scaled by 1/TEMP=20) -> fp16 scratch.
//  K2: persistent HMMA GEMM. BM=BN=128, BK=64, 3 stages, mbarrier pipeline,
//      128-thread CTAs (4 warps, 2x2 of 64x64 warp tiles), 2 CTA/SM (= R8).
//      NEW (R11): cutlass-style fragment prefetch. A-fragments double-buffered
//      (ks+1's A ldsm issued before ks's MMAs); the full[next-stage] wait is
//      moved between ks2 and ks3 with next stage's ks0 A-fragments prefetched
//      before ks3's MMAs -> no scheduling wall at iteration boundaries.
//      B consumed ldsm-by-ldsm (4 live regs) to pay for the A double buffer.

#define NROWS 4096
#define DDIM  1024
#define BM 128
#define BN 128
#define BK 64
#define NSTAGE 3
#define KITERS (DDIM / BK)              // 16
#define STAGE_BYTES ((BM + BN) * 128)   // 32 KB
#define SMEM_ST0 1024
#define SMEM_DYN (SMEM_ST0 + NSTAGE * STAGE_BYTES)
#define NTILES ((NROWS / BM) * (NROWS / BN))   // 1024
#define GRID_P 296                      // 2 x 148 SMs
#define NTHREADS 128

__device__ __align__(1024) __half g_xh[NROWS * DDIM];
__device__ __align__(1024) __half g_yh[NROWS * DDIM];

__device__ __forceinline__ uint32_t smem_u32(const void* p) {
    uint32_t a;
    asm("{ .reg .u64 t; cvta.to.shared.u64 t, %1; cvt.u32.u64 %0, t; }" : "=r"(a) : "l"(p));
    return a;
}

#define CP_ASYNC16(dst, src) \
    asm volatile("cp.async.cg.shared.global [%0], [%1], 16;" :: "r"(dst), "l"(src))
#define CP_ASYNC_ARRIVE_NOINC(mbar) \
    asm volatile("cp.async.mbarrier.arrive.noinc.shared.b64 [%0];" :: "r"(mbar) : "memory")

#define MBAR_INIT(addr, cnt) \
    asm volatile("mbarrier.init.shared.b64 [%0], %1;" :: "r"(addr), "r"(cnt) : "memory")
#define MBAR_ARRIVE(addr) \
    asm volatile("mbarrier.arrive.shared.b64 _, [%0];" :: "r"(addr) : "memory")

#define MBAR_WAIT(addr, par) do {                                                  \
    uint32_t _m = (addr); uint32_t _p = (par); uint32_t _done;                     \
    asm volatile("{\n\t.reg .pred p;\n\t"                                          \
        "mbarrier.try_wait.parity.acquire.cta.shared::cta.b64 p, [%1], %2;\n\t"    \
        "selp.b32 %0, 1, 0, p;\n\t}"                                               \
        : "=r"(_done) : "r"(_m), "r"(_p) : "memory");                              \
    if (!_done) {                                                                  \
        asm volatile("{\n\t.reg .pred P1;\n\t"                                     \
            "WL_%=:\n\t"                                                           \
            "mbarrier.try_wait.parity.acquire.cta.shared::cta.b64 P1, [%0], %1, 0x989680;\n\t" \
            "@P1 bra.uni WD_%=;\n\t"                                               \
            "bra.uni WL_%=;\n\t"                                                   \
            "WD_%=:\n\t}" :: "r"(_m), "r"(_p) : "memory");                         \
    }                                                                              \
} while (0)

// Relaxed variant for producer empty-waits (post-wait accesses are cp.async only)
#define MBAR_WAIT_RLX(addr, par) do {                                              \
    uint32_t _m = (addr); uint32_t _p = (par); uint32_t _done;                     \
    asm volatile("{\n\t.reg .pred p;\n\t"                                          \
        "mbarrier.try_wait.parity.relaxed.cta.shared::cta.b64 p, [%1], %2, 0x989680;\n\t" \
        "selp.b32 %0, 1, 0, p;\n\t}"                                               \
        : "=r"(_done) : "r"(_m), "r"(_p) : "memory");                              \
    if (!_done) {                                                                  \
        asm volatile("{\n\t.reg .pred P1;\n\t"                                     \
            "WL_%=:\n\t"                                                           \
            "mbarrier.try_wait.parity.relaxed.cta.shared::cta.b64 P1, [%0], %1, 0x989680;\n\t" \
            "@P1 bra.uni WD_%=;\n\t"                                               \
            "bra.uni WL_%=;\n\t"                                                   \
            "WD_%=:\n\t}" :: "r"(_m), "r"(_p) : "memory");                         \
    }                                                                              \
} while (0)

__device__ __forceinline__ uint32_t swz(uint32_t off) {
    return off ^ ((off >> 3) & 0x70);
}

__device__ __forceinline__ void ldsm_x4(uint32_t* r, uint32_t addr) {
    asm volatile("ldmatrix.sync.aligned.m8n8.x4.shared.b16 {%0,%1,%2,%3}, [%4];"
                 : "=r"(r[0]), "=r"(r[1]), "=r"(r[2]), "=r"(r[3]) : "r"(addr));
}

__device__ __forceinline__ void mma16816(float* c, const uint32_t* a, const uint32_t* b) {
    asm volatile(
        "mma.sync.aligned.m16n8k16.row.col.f32.f16.f16.f32 "
        "{%0,%1,%2,%3}, {%4,%5,%6,%7}, {%8,%9}, {%0,%1,%2,%3};"
        : "+f"(c[0]), "+f"(c[1]), "+f"(c[2]), "+f"(c[3])
        : "r"(a[0]), "r"(a[1]), "r"(a[2]), "r"(a[3]), "r"(b[0]), "r"(b[1]));
}

// ---------------------------------------------------------------------------
// Kernel 1: row normalization -> fp16 (one 256-thread block per row)
// ---------------------------------------------------------------------------
__global__ void norm_kernel(const float* __restrict__ x, const float* __restrict__ y) {
    int row = blockIdx.x;
    const float4* src; __half2* dst; float extra;
    if (row < NROWS) {
        src = (const float4*)(x + (size_t)row * DDIM);
        dst = (__half2*)(g_xh + (size_t)row * DDIM);
        extra = 20.0f;                  // 1/TEMP folded into x side
    } else {
        int r = row - NROWS;
        src = (const float4*)(y + (size_t)r * DDIM);
        dst = (__half2*)(g_yh + (size_t)r * DDIM);
        extra = 1.0f;
    }
    int t = threadIdx.x;
    float4 v = src[t];
    float ss = v.x * v.x + v.y * v.y + v.z * v.z + v.w * v.w;
    #pragma unroll
    for (int o = 16; o > 0; o >>= 1) ss += __shfl_xor_sync(0xffffffffu, ss, o);

    __shared__ float wss[8];
    __shared__ float sinv;
    if ((t & 31) == 0) wss[t >> 5] = ss;
    __syncthreads();
    if (t == 0) {
        float tot = 0.0f;
        #pragma unroll
        for (int i = 0; i < 8; i++) tot += wss[i];
        sinv = extra / fmaxf(sqrtf(tot), 1e-8f);
    }
    __syncthreads();
    float inv = sinv;
    dst[2 * t]     = __floats2half2_rn(v.x * inv, v.y * inv);
    dst[2 * t + 1] = __floats2half2_rn(v.z * inv, v.w * inv);
}

// ---------------------------------------------------------------------------
// Kernel 2: persistent HMMA GEMM, 4 warps/CTA, warp tile 64x64, 2 CTA/SM,
//           A-fragment double buffering + cross-stage prefetch
// ---------------------------------------------------------------------------
__global__ void __launch_bounds__(NTHREADS, 2) gemm_kernel(float* __restrict__ C) {
    extern __shared__ __align__(1024) char smem[];
    const uint32_t smem_base = smem_u32(smem);
    const int tid = threadIdx.x;
    const int wid = tid >> 5;
    const int lid = tid & 31;

    const int wm = wid & 1;              // m band (64 rows each)
    const int wn = wid >> 1;             // n band (64 cols each)

    // barriers: full[s] @ base + s*8 ; empty[s] @ base + 24 + s*8
    if (tid == 0) {
        #pragma unroll
        for (int s = 0; s < NSTAGE; s++) {
            MBAR_INIT(smem_base + s * 8, NTHREADS); // full: one noinc arrive/thread
            MBAR_INIT(smem_base + 24 + s * 8, 4);   // empty: one arrive/warp
        }
    }
    __syncthreads();

    // ldmatrix lane geometry
    const int g   = lid >> 3;
    const int rin = lid & 7;
    const int a_m  = (g & 1) * 8 + rin;
    const int a_kb = (g >> 1) * 16;
    const int b_n  = (g >> 1) * 8 + rin;
    const int b_kb = (g & 1) * 16;

    uint32_t a_rowoff[4], b_rowoff[4];
    #pragma unroll
    for (int t = 0; t < 4; t++)
        a_rowoff[t] = (uint32_t)(wm * 64 + t * 16 + a_m) * 128;
    #pragma unroll
    for (int p = 0; p < 4; p++)
        b_rowoff[p] = (uint32_t)(BM + wn * 64 + p * 16 + b_n) * 128;

    // Stage loader for (tile lt, k-slice lk): 2048 chunks / 128 thr = 16 each.
    auto load_stage = [&](int sbuf, int lt, int lk) {
        uint32_t sbase = smem_base + SMEM_ST0 + sbuf * STAGE_BYTES;
        const char* ag = (const char*)g_xh
            + ((size_t)(lt >> 5) * BM) * (DDIM * 2) + lk * (BK * 2);
        const char* bg = (const char*)g_yh
            + ((size_t)(lt & 31) * BN) * (DDIM * 2) + lk * (BK * 2);
        #pragma unroll
        for (int k = 0; k < 16; k++) {
            int i = tid + k * NTHREADS;
            int r = (i >> 3) & 127;
            int c = (i & 7) * 16;
            uint32_t off = swz((uint32_t)((i < 1024 ? r : BM + r) * 128 + c));
            const char* src = (i < 1024 ? ag : bg) + (size_t)r * (DDIM * 2) + c;
            CP_ASYNC16(sbase + off, src);
        }
        CP_ASYNC_ARRIVE_NOINC(smem_base + sbuf * 8);
    };

    float acc[4][8][4];
    #pragma unroll
    for (int mt = 0; mt < 4; mt++)
        #pragma unroll
        for (int nt = 0; nt < 8; nt++)
            #pragma unroll
            for (int q = 0; q < 4; q++)
                acc[mt][nt][q] = 0.0f;

    // A-fragment double buffer
    uint32_t A0[4][4], A1[4][4];

    // Load A fragments for (stage base, ks) into dst
    auto ldsm_A = [&](uint32_t sbase, int ks, uint32_t (&dst)[4][4]) {
        const uint32_t kb = (uint32_t)ks * 32;
        #pragma unroll
        for (int t = 0; t < 4; t++)
            ldsm_x4(dst[t], sbase + swz(a_rowoff[t] + kb + a_kb));
    };
    // B ldsm + MMAs for one ks step, consuming B ldsm-by-ldsm (4 live regs)
    auto mma_ks = [&](uint32_t sbase, int ks, uint32_t (&aC)[4][4]) {
        const uint32_t kb = (uint32_t)ks * 32;
        #pragma unroll
        for (int p = 0; p < 4; p++) {
            uint32_t r[4];
            ldsm_x4(r, sbase + swz(b_rowoff[p] + kb + b_kb));
            #pragma unroll
            for (int mt = 0; mt < 4; mt++) {
                mma16816(acc[mt][2 * p],     aC[mt], r);
                mma16816(acc[mt][2 * p + 1], aC[mt], r + 2);
            }
        }
    };

    int tile = blockIdx.x;
    int lt = tile, lk = 0;
    // Prologue: stages 0,1 of first tile (fresh empty barriers: no wait needed)
    load_stage(0, lt, 0);
    load_stage(1, lt, 1);
    lk = 2;

    int sb = 0;               // consumer: stage being processed
    int nsb = 1, nfpar = 0;   // next full-wait pointer (stage, parity)
    int lb = 2, epar = 1;     // producer: buffer + empty-parity (first waits pass)

    // Prologue consumer: wait stage 0, prefetch its ks0 A frags into A0
    MBAR_WAIT(smem_base + 0 * 8, 0);
    ldsm_A(smem_base + SMEM_ST0, 0, A0);

    while (tile < NTILES) {
        const bool lastTile = (tile + GRID_P >= NTILES);
        for (int it = 0; it < KITERS; ++it) {
            // Producer: refill next buffer (waits only on 3-ago consumption)
            if (lt < NTILES) {
                MBAR_WAIT_RLX(smem_base + 24 + lb * 8, epar);
                load_stage(lb, lt, lk);
                if (++lk == KITERS) { lk = 0; lt += GRID_P; }
                if (++lb == NSTAGE) { lb = 0; epar ^= 1; }
            }

            const uint32_t sbase = smem_base + SMEM_ST0 + sb * STAGE_BYTES;
            // ks0..ks2: prefetch next ks's A before this ks's B/MMA block
            ldsm_A(sbase, 1, A1);  mma_ks(sbase, 0, A0);
            ldsm_A(sbase, 2, A0);  mma_ks(sbase, 1, A1);
            ldsm_A(sbase, 3, A1);  mma_ks(sbase, 2, A0);
            // ks3: cross-stage — wait next stage's data, prefetch its ks0 A
            const bool last = lastTile && (it == KITERS - 1);
            if (!last) {
                MBAR_WAIT(smem_base + nsb * 8, nfpar);
                ldsm_A(smem_base + SMEM_ST0 + nsb * STAGE_BYTES, 0, A0);
                if (++nsb == NSTAGE) { nsb = 0; nfpar ^= 1; }
            }
            mma_ks(sbase, 3, A1);

            // This warp is done reading stage sb
            __syncwarp();
            if (lid == 0) MBAR_ARRIVE(smem_base + 24 + sb * 8);
            if (++sb == NSTAGE) sb = 0;
        }

        // Epilogue for this tile (overlaps in-flight loads of next tile)
        {
            const int rowA0 = (tile >> 5) * BM;
            const int rowB0 = (tile & 31) * BN;
            const int crow = rowA0 + wm * 64 + (lid >> 2);
            const int ccol = rowB0 + wn * 64 + (lid & 3) * 2;
            #pragma unroll
            for (int mt = 0; mt < 4; mt++) {
                #pragma unroll
                for (int nt = 0; nt < 8; nt++) {
                    float* p0 = C + (size_t)(crow + mt * 16) * NROWS + ccol + nt * 8;
                    float* p1 = p0 + 8 * NROWS;
                    *(float2*)p0 = make_float2(acc[mt][nt][0], acc[mt][nt][1]);
                    *(float2*)p1 = make_float2(acc[mt][nt][2], acc[mt][nt][3]);
                    acc[mt][nt][0] = 0.0f; acc[mt][nt][1] = 0.0f;
                    acc[mt][nt][2] = 0.0f; acc[mt][nt][3] = 0.0f;
                }
            }
        }
        tile += GRID_P;
    }
}

// ---------------------------------------------------------------------------
extern "C" void kernel_launch(void* const* d_in, const int* in_sizes, int n_in,
                              void* d_out, int out_size) {
    const float* x = (const float*)d_in[0];
    const float* y = (const float*)d_in[1];
    float* out = (float*)d_out;

    cudaFuncSetAttribute(gemm_kernel, cudaFuncAttributeMaxDynamicSharedMemorySize, SMEM_DYN);

    norm_kernel<<<2 * NROWS, 256>>>(x, y);
    gemm_kernel<<<GRID_P, NTHREADS, SMEM_DYN>>>(out);
}